// round 8
// baseline (speedup 1.0000x reference)
#include <cuda_runtime.h>
#include <stdint.h>

#define NN      8192
#define EE      262144
#define IN_NODE 11
#define IN_EDGE 4
#define H_NF    4
#define OUT_NF  4
#define EMB_NF  2
#define NREP    8

#define GRID    512
#define TPB     256
#define ROWS    8           // rows per row-block in phase 3
#define EPT     2           // edges per thread in phase 1  (GRID*TPB*EPT == EE)

// Scratch -------------------------------------------------------------------
// Invariant: g_acc all-zero at entry of every kernel_launch call
// (zero at load; phase 2 re-zeroes). Barrier state returns to {0,0} each call.
__device__ float2   g_acc[NREP][NN];
__device__ float    g_emb2[NN * EMB_NF];
__device__ unsigned g_count = 0;
__device__ volatile unsigned g_sense = 0;

// ---------------------------------------------------------------------------
// Grid-wide sense barrier. All GRID CTAs are co-resident (512 CTAs x 256thr,
// 0 smem). Sense toggles 0->1->0 across the two uses, so state is identical
// at every kernel entry (graph-replay safe).
// ---------------------------------------------------------------------------
__device__ __forceinline__ void grid_bar(unsigned want) {
    __syncthreads();
    if (threadIdx.x == 0) {
        __threadfence();
        unsigned arrived = atomicAdd(&g_count, 1u);
        if (arrived == GRID - 1) {
            g_count = 0;
            __threadfence();
            g_sense = want;
        } else {
            while (g_sense != want) __nanosleep(32);
        }
        __threadfence();
    }
    __syncthreads();
}

// M[a][c] = sum_b W2[a][b] * We[b][c]
__device__ __forceinline__ void fuse_W2We(const float* __restrict__ W2,
                                          const float* __restrict__ We,
                                          float M[H_NF][EMB_NF]) {
#pragma unroll
    for (int a = 0; a < H_NF; a++)
#pragma unroll
        for (int c = 0; c < EMB_NF; c++) {
            float acc = 0.0f;
#pragma unroll
            for (int b = 0; b < OUT_NF; b++)
                acc += __ldg(&W2[a * OUT_NF + b]) * __ldg(&We[b * EMB_NF + c]);
            M[a][c] = acc;
        }
}

// ---------------------------------------------------------------------------
// One persistent kernel: scatter -> bar -> emb -> bar -> all-pairs.
// ---------------------------------------------------------------------------
__global__ void __launch_bounds__(TPB) k_fused(
        const float* __restrict__ node_feats,
        const int* __restrict__ edge_index, const float* __restrict__ edge_attr,
        const float* __restrict__ W1, const float* __restrict__ b1,
        const float* __restrict__ W2, const float* __restrict__ b2,
        const float* __restrict__ We, const float* __restrict__ be,
        float* __restrict__ adj, float* __restrict__ out_emb) {
    const int tid = blockIdx.x * TPB + threadIdx.x;

    // ===== Phase 1: edge scatter (edge_attr @ Wf_edge -> replicated acc) ====
    {
        float M[H_NF][EMB_NF];
        fuse_W2We(W2, We, M);
        float wfe[IN_EDGE][EMB_NF];
#pragma unroll
        for (int r = 0; r < IN_EDGE; r++)
#pragma unroll
            for (int c = 0; c < EMB_NF; c++) {
                float acc = 0.0f;
#pragma unroll
                for (int a = 0; a < H_NF; a++)
                    acc += __ldg(&W1[(IN_NODE + r) * H_NF + a]) * M[a][c];
                wfe[r][c] = acc;
            }

        const int rep = blockIdx.x & (NREP - 1);
        int2 idx = reinterpret_cast<const int2*>(edge_index)[tid];   // edges 2t,2t+1
#pragma unroll
        for (int u = 0; u < EPT; u++) {
            int e  = tid * EPT + u;
            int rr = (u == 0) ? idx.x : idx.y;
            float4 a = reinterpret_cast<const float4*>(edge_attr)[e];
            float cx = a.x * wfe[0][0] + a.y * wfe[1][0] + a.z * wfe[2][0] + a.w * wfe[3][0];
            float cy = a.x * wfe[0][1] + a.y * wfe[1][1] + a.z * wfe[2][1] + a.w * wfe[3][1];
            float2* dst = &g_acc[rep][rr];
            asm volatile("red.global.add.v2.f32 [%0], {%1, %2};"
                         :: "l"(dst), "f"(cx), "f"(cy) : "memory");
        }
    }

    grid_bar(1u);

    // ===== Phase 2: node embeddings (first 32 CTAs), re-zero accumulators ===
    if (tid < NN) {
        float M[H_NF][EMB_NF];
        fuse_W2We(W2, We, M);
        float wfn[IN_NODE][EMB_NF];
#pragma unroll
        for (int k = 0; k < IN_NODE; k++)
#pragma unroll
            for (int c = 0; c < EMB_NF; c++) {
                float acc = 0.0f;
#pragma unroll
                for (int a = 0; a < H_NF; a++)
                    acc += __ldg(&W1[k * H_NF + a]) * M[a][c];
                wfn[k][c] = acc;
            }
        float bf[EMB_NF];
#pragma unroll
        for (int c = 0; c < EMB_NF; c++) {
            float acc = __ldg(&be[c]);
#pragma unroll
            for (int b = 0; b < OUT_NF; b++) {
                float hb = __ldg(&b2[b]);
#pragma unroll
                for (int a = 0; a < H_NF; a++)
                    hb += __ldg(&b1[a]) * __ldg(&W2[a * OUT_NF + b]);
                acc += hb * __ldg(&We[b * EMB_NF + c]);
            }
            bf[c] = acc;
        }

        float ex = bf[0], ey = bf[1];
#pragma unroll
        for (int r = 0; r < NREP; r++) {
            float2 v = __ldcg(&g_acc[r][tid]);   // L2 read (RED results live in L2)
            ex += v.x;  ey += v.y;
            g_acc[r][tid] = make_float2(0.0f, 0.0f);   // restore invariant
        }
#pragma unroll
        for (int k = 0; k < IN_NODE; k++) {
            float nf = node_feats[tid * IN_NODE + k];
            ex += nf * wfn[k][0];
            ey += nf * wfn[k][1];
        }
        g_emb2[tid * 2 + 0] = ex;
        g_emb2[tid * 2 + 1] = ey;
        out_emb[tid * 2 + 0] = ex;
        out_emb[tid * 2 + 1] = ey;
    }

    grid_bar(0u);

    // ===== Phase 3: all-pairs adjacency (dot-product + tanh form) ===========
    //   5d-0.5 = K_i + a_j - 10*ei.ej ;  sigmoid(10d-1) = 0.5*tanh(5d-0.5)+0.5
    const float2* emb2 = reinterpret_cast<const float2*>(g_emb2);
    const float4* embq = reinterpret_cast<const float4*>(g_emb2);

    for (int blk = blockIdx.x; blk < NN / ROWS; blk += GRID) {
        const int i0 = blk * ROWS;
        float Kc[ROWS], bx[ROWS], by[ROWS];
#pragma unroll
        for (int r = 0; r < ROWS; r++) {
            float2 e = __ldcg(&emb2[i0 + r]);
            Kc[r] = fmaf(5.0f, fmaf(e.y, e.y, e.x * e.x), -0.5f);
            bx[r] = -10.0f * e.x;
            by[r] = -10.0f * e.y;
        }

        for (int g = threadIdx.x; g < NN / 4; g += TPB) {
            const int j0 = g * 4;
            float2 ej[4];
            float  aj[4];
#pragma unroll
            for (int q = 0; q < 2; q++) {
                float4 v = __ldcg(&embq[g * 2 + q]);
                ej[q * 2 + 0] = make_float2(v.x, v.y);
                ej[q * 2 + 1] = make_float2(v.z, v.w);
            }
#pragma unroll
            for (int c = 0; c < 4; c++)
                aj[c] = 5.0f * fmaf(ej[c].y, ej[c].y, ej[c].x * ej[c].x);

#pragma unroll
            for (int r = 0; r < ROWS; r++) {
                float o[4];
#pragma unroll
                for (int c = 0; c < 4; c++) {
                    float t = Kc[r] + aj[c];
                    t = fmaf(bx[r], ej[c].x, t);
                    t = fmaf(by[r], ej[c].y, t);
                    float th;
                    asm("tanh.approx.f32 %0, %1;" : "=f"(th) : "f"(t));
                    o[c] = fmaf(th, 0.5f, 0.5f);
                }
                __stcs(reinterpret_cast<float4*>(adj + (size_t)(i0 + r) * NN + j0),
                       make_float4(o[0], o[1], o[2], o[3]));
            }
        }

        __syncthreads();
        if (threadIdx.x < ROWS) {
            int i = i0 + threadIdx.x;
            adj[(size_t)i * NN + i] = 0.0f;
        }
        __syncthreads();
    }
}

// ---------------------------------------------------------------------------
extern "C" void kernel_launch(void* const* d_in, const int* in_sizes, int n_in,
                              void* d_out, int out_size) {
    const float* node_feats = (const float*)d_in[0];
    const int*   edge_index = (const int*)d_in[1];
    const float* edge_attr  = (const float*)d_in[2];
    const float* W1 = (const float*)d_in[3];
    const float* b1 = (const float*)d_in[4];
    const float* W2 = (const float*)d_in[5];
    const float* b2 = (const float*)d_in[6];
    const float* We = (const float*)d_in[7];
    const float* be = (const float*)d_in[8];

    float* adj     = (float*)d_out;                       // [N, N]
    float* out_emb = (float*)d_out + (size_t)NN * NN;     // [N, 2]

    k_fused<<<GRID, TPB>>>(node_feats, edge_index, edge_attr,
                           W1, b1, W2, b2, We, be, adj, out_emb);
}

// round 9
// speedup vs baseline: 1.2299x; 1.2299x over previous
#include <cuda_runtime.h>
#include <stdint.h>

#define NN      8192
#define EE      262144
#define IN_NODE 11
#define IN_EDGE 4
#define H_NF    4
#define OUT_NF  4
#define EMB_NF  2
#define NREP    8

#define ROWS    8          // rows per CTA in k_pair
#define EPT     2          // edges per thread in k_scatter

// Scratch -------------------------------------------------------------------
// Invariant: g_acc is all-zero at entry of every kernel_launch call.
// (Zero at module load; k_emb re-zeroes after consuming.)
__device__ float2 g_acc[NREP][NN];
__device__ float  g_emb2[NN * EMB_NF];

// M[a][c] = sum_b W2[a][b] * We[b][c]
__device__ __forceinline__ void fuse_W2We(const float* __restrict__ W2,
                                          const float* __restrict__ We,
                                          float M[H_NF][EMB_NF]) {
#pragma unroll
    for (int a = 0; a < H_NF; a++)
#pragma unroll
        for (int c = 0; c < EMB_NF; c++) {
            float acc = 0.0f;
#pragma unroll
            for (int b = 0; b < OUT_NF; b++)
                acc += __ldg(&W2[a * OUT_NF + b]) * __ldg(&We[b * EMB_NF + c]);
            M[a][c] = acc;
        }
}

// ---------------------------------------------------------------------------
// Kernel 1: scatter. EPT=2 edges/thread, int2 index load, 512 CTAs (high
// occupancy), two independent LDG->RED chains per thread, 8-way replicated acc.
// ---------------------------------------------------------------------------
__global__ void __launch_bounds__(256) k_scatter(
        const int* __restrict__ edge_index, const float* __restrict__ edge_attr,
        const float* __restrict__ W1, const float* __restrict__ W2,
        const float* __restrict__ We) {
    float M[H_NF][EMB_NF];
    fuse_W2We(W2, We, M);
    float wfe[IN_EDGE][EMB_NF];
#pragma unroll
    for (int r = 0; r < IN_EDGE; r++)
#pragma unroll
        for (int c = 0; c < EMB_NF; c++) {
            float acc = 0.0f;
#pragma unroll
            for (int a = 0; a < H_NF; a++)
                acc += __ldg(&W1[(IN_NODE + r) * H_NF + a]) * M[a][c];
            wfe[r][c] = acc;
        }

    const int tid = blockIdx.x * blockDim.x + threadIdx.x;
    const int rep = blockIdx.x & (NREP - 1);

    int2 idx = reinterpret_cast<const int2*>(edge_index)[tid];   // edges 2t, 2t+1
    float4 a0 = reinterpret_cast<const float4*>(edge_attr)[tid * EPT + 0];
    float4 a1 = reinterpret_cast<const float4*>(edge_attr)[tid * EPT + 1];

    float cx0 = a0.x * wfe[0][0] + a0.y * wfe[1][0] + a0.z * wfe[2][0] + a0.w * wfe[3][0];
    float cy0 = a0.x * wfe[0][1] + a0.y * wfe[1][1] + a0.z * wfe[2][1] + a0.w * wfe[3][1];
    float cx1 = a1.x * wfe[0][0] + a1.y * wfe[1][0] + a1.z * wfe[2][0] + a1.w * wfe[3][0];
    float cy1 = a1.x * wfe[0][1] + a1.y * wfe[1][1] + a1.z * wfe[2][1] + a1.w * wfe[3][1];

    float2* d0 = &g_acc[rep][idx.x];
    float2* d1 = &g_acc[rep][idx.y];
    asm volatile("red.global.add.v2.f32 [%0], {%1, %2};"
                 :: "l"(d0), "f"(cx0), "f"(cy0) : "memory");
    asm volatile("red.global.add.v2.f32 [%0], {%1, %2};"
                 :: "l"(d1), "f"(cx1), "f"(cy1) : "memory");
}

// ---------------------------------------------------------------------------
// Kernel 2: per-node embedding; sums replicas, re-zeroes them.
// ---------------------------------------------------------------------------
__global__ void __launch_bounds__(256) k_emb(
        const float* __restrict__ node_feats,
        const float* __restrict__ W1, const float* __restrict__ b1,
        const float* __restrict__ W2, const float* __restrict__ b2,
        const float* __restrict__ We, const float* __restrict__ be,
        float* __restrict__ out_emb) {
    float M[H_NF][EMB_NF];
    fuse_W2We(W2, We, M);
    float wfn[IN_NODE][EMB_NF];
#pragma unroll
    for (int k = 0; k < IN_NODE; k++)
#pragma unroll
        for (int c = 0; c < EMB_NF; c++) {
            float acc = 0.0f;
#pragma unroll
            for (int a = 0; a < H_NF; a++)
                acc += __ldg(&W1[k * H_NF + a]) * M[a][c];
            wfn[k][c] = acc;
        }
    float bf[EMB_NF];
#pragma unroll
    for (int c = 0; c < EMB_NF; c++) {
        float acc = __ldg(&be[c]);
#pragma unroll
        for (int b = 0; b < OUT_NF; b++) {
            float hb = __ldg(&b2[b]);
#pragma unroll
            for (int a = 0; a < H_NF; a++)
                hb += __ldg(&b1[a]) * __ldg(&W2[a * OUT_NF + b]);
            acc += hb * __ldg(&We[b * EMB_NF + c]);
        }
        bf[c] = acc;
    }

    int i = blockIdx.x * blockDim.x + threadIdx.x;
    if (i >= NN) return;
    float ex = bf[0], ey = bf[1];
#pragma unroll
    for (int r = 0; r < NREP; r++) {
        float2 v = g_acc[r][i];
        ex += v.x;  ey += v.y;
        g_acc[r][i] = make_float2(0.0f, 0.0f);   // restore invariant
    }
#pragma unroll
    for (int k = 0; k < IN_NODE; k++) {
        float nf = node_feats[i * IN_NODE + k];
        ex += nf * wfn[k][0];
        ey += nf * wfn[k][1];
    }
    g_emb2[i * 2 + 0] = ex;
    g_emb2[i * 2 + 1] = ey;
    out_emb[i * 2 + 0] = ex;
    out_emb[i * 2 + 1] = ey;
}

// ---------------------------------------------------------------------------
// Kernel 3: all-pairs adjacency, dot-product form (unchanged from R7; it runs
// at the LTS/DRAM write cap).
//   5d - 0.5 = K_i + a_j - 10*ei.ej ;  sigmoid(10d-1) = 0.5*tanh(5d-0.5)+0.5
// ---------------------------------------------------------------------------
__global__ void __launch_bounds__(256) k_pair(float* __restrict__ adj) {
    const int i0 = blockIdx.x * ROWS;
    float Kc[ROWS], bx[ROWS], by[ROWS];
#pragma unroll
    for (int r = 0; r < ROWS; r++) {
        float2 e = reinterpret_cast<const float2*>(g_emb2)[i0 + r];
        Kc[r] = fmaf(5.0f, fmaf(e.y, e.y, e.x * e.x), -0.5f);
        bx[r] = -10.0f * e.x;
        by[r] = -10.0f * e.y;
    }

    const float4* embq = reinterpret_cast<const float4*>(g_emb2);

    for (int g = threadIdx.x; g < NN / 4; g += blockDim.x) {
        const int j0 = g * 4;
        float2 ej[4];
        float  aj[4];
#pragma unroll
        for (int q = 0; q < 2; q++) {
            float4 v = embq[g * 2 + q];
            ej[q * 2 + 0] = make_float2(v.x, v.y);
            ej[q * 2 + 1] = make_float2(v.z, v.w);
        }
#pragma unroll
        for (int c = 0; c < 4; c++)
            aj[c] = 5.0f * fmaf(ej[c].y, ej[c].y, ej[c].x * ej[c].x);

#pragma unroll
        for (int r = 0; r < ROWS; r++) {
            float o[4];
#pragma unroll
            for (int c = 0; c < 4; c++) {
                float t = Kc[r] + aj[c];
                t = fmaf(bx[r], ej[c].x, t);
                t = fmaf(by[r], ej[c].y, t);
                float th;
                asm("tanh.approx.f32 %0, %1;" : "=f"(th) : "f"(t));
                o[c] = fmaf(th, 0.5f, 0.5f);
            }
            __stcs(reinterpret_cast<float4*>(adj + (size_t)(i0 + r) * NN + j0),
                   make_float4(o[0], o[1], o[2], o[3]));
        }
    }

    __syncthreads();
    if (threadIdx.x < ROWS) {
        int i = i0 + threadIdx.x;
        adj[(size_t)i * NN + i] = 0.0f;
    }
}

// ---------------------------------------------------------------------------
extern "C" void kernel_launch(void* const* d_in, const int* in_sizes, int n_in,
                              void* d_out, int out_size) {
    const float* node_feats = (const float*)d_in[0];
    const int*   edge_index = (const int*)d_in[1];
    const float* edge_attr  = (const float*)d_in[2];
    const float* W1 = (const float*)d_in[3];
    const float* b1 = (const float*)d_in[4];
    const float* W2 = (const float*)d_in[5];
    const float* b2 = (const float*)d_in[6];
    const float* We = (const float*)d_in[7];
    const float* be = (const float*)d_in[8];

    float* adj     = (float*)d_out;                       // [N, N]
    float* out_emb = (float*)d_out + (size_t)NN * NN;     // [N, 2]

    k_scatter<<<EE / EPT / 256, 256>>>(edge_index, edge_attr, W1, W2, We);
    k_emb<<<NN / 256, 256>>>(node_feats, W1, b1, W2, b2, We, be, out_emb);
    k_pair<<<NN / ROWS, 256>>>(adj);
}

// round 10
// speedup vs baseline: 1.2471x; 1.0140x over previous
#include <cuda_runtime.h>
#include <stdint.h>

#define NN      8192
#define EE      262144
#define IN_NODE 11
#define IN_EDGE 4
#define H_NF    4
#define OUT_NF  4
#define EMB_NF  2
#define NREP    8

#define ROWS    8          // rows per CTA in k_pair
#define EPT     2          // edges per thread in k_scatter

// Scratch -------------------------------------------------------------------
// Invariant: g_acc is all-zero at entry of every kernel_launch call.
// (Zero at module load; k_emb re-zeroes after consuming.)
__device__ float2 g_acc[NREP][NN];
__device__ float  g_emb2[NN * EMB_NF];

// One fused-weight entry: wf[r][c] = sum_a W1[r][a] * (sum_b W2[a][b]*We[b][c])
__device__ __forceinline__ float fused_w_entry(const float* __restrict__ W1,
                                               const float* __restrict__ W2,
                                               const float* __restrict__ We,
                                               int r, int c) {
    float acc = 0.0f;
#pragma unroll
    for (int a = 0; a < H_NF; a++) {
        float m = 0.0f;
#pragma unroll
        for (int b = 0; b < OUT_NF; b++)
            m += __ldg(&W2[a * OUT_NF + b]) * __ldg(&We[b * EMB_NF + c]);
        acc += __ldg(&W1[r * H_NF + a]) * m;
    }
    return acc;
}

// ---------------------------------------------------------------------------
// Kernel 1: scatter. Warp 0 computes the 8 fused edge-weights into smem
// (once per CTA); every thread then does a lean body: int2 idx load, two
// float4 attr loads, 16 FMA, two red.v2 into the 8-way replicated acc.
// ---------------------------------------------------------------------------
__global__ void __launch_bounds__(256) k_scatter(
        const int* __restrict__ edge_index, const float* __restrict__ edge_attr,
        const float* __restrict__ W1, const float* __restrict__ W2,
        const float* __restrict__ We) {
    __shared__ float s_wfe[IN_EDGE * EMB_NF];          // [r][c] -> r*2+c
    if (threadIdx.x < IN_EDGE * EMB_NF) {
        int r = threadIdx.x >> 1, c = threadIdx.x & 1;
        s_wfe[threadIdx.x] = fused_w_entry(W1, W2, We, IN_NODE + r, c);
    }
    __syncthreads();

    const float w00 = s_wfe[0], w01 = s_wfe[1];
    const float w10 = s_wfe[2], w11 = s_wfe[3];
    const float w20 = s_wfe[4], w21 = s_wfe[5];
    const float w30 = s_wfe[6], w31 = s_wfe[7];

    const int tid = blockIdx.x * blockDim.x + threadIdx.x;
    const int rep = blockIdx.x & (NREP - 1);

    int2 idx = reinterpret_cast<const int2*>(edge_index)[tid];   // edges 2t, 2t+1
    float4 a0 = reinterpret_cast<const float4*>(edge_attr)[tid * EPT + 0];
    float4 a1 = reinterpret_cast<const float4*>(edge_attr)[tid * EPT + 1];

    float cx0 = fmaf(a0.x, w00, fmaf(a0.y, w10, fmaf(a0.z, w20, a0.w * w30)));
    float cy0 = fmaf(a0.x, w01, fmaf(a0.y, w11, fmaf(a0.z, w21, a0.w * w31)));
    float cx1 = fmaf(a1.x, w00, fmaf(a1.y, w10, fmaf(a1.z, w20, a1.w * w30)));
    float cy1 = fmaf(a1.x, w01, fmaf(a1.y, w11, fmaf(a1.z, w21, a1.w * w31)));

    float2* d0 = &g_acc[rep][idx.x];
    float2* d1 = &g_acc[rep][idx.y];
    asm volatile("red.global.add.v2.f32 [%0], {%1, %2};"
                 :: "l"(d0), "f"(cx0), "f"(cy0) : "memory");
    asm volatile("red.global.add.v2.f32 [%0], {%1, %2};"
                 :: "l"(d1), "f"(cx1), "f"(cy1) : "memory");
}

// ---------------------------------------------------------------------------
// Kernel 2: per-node embedding. Cooperative weight fusion in smem (24 lanes),
// then lean per-node body; sums replicas and re-zeroes them.
// ---------------------------------------------------------------------------
__global__ void __launch_bounds__(256) k_emb(
        const float* __restrict__ node_feats,
        const float* __restrict__ W1, const float* __restrict__ b1,
        const float* __restrict__ W2, const float* __restrict__ b2,
        const float* __restrict__ We, const float* __restrict__ be,
        float* __restrict__ out_emb) {
    __shared__ float s_wfn[IN_NODE * EMB_NF];          // [k][c] -> k*2+c
    __shared__ float s_bf[EMB_NF];
    if (threadIdx.x < IN_NODE * EMB_NF) {
        int k = threadIdx.x >> 1, c = threadIdx.x & 1;
        s_wfn[threadIdx.x] = fused_w_entry(W1, W2, We, k, c);
    } else if (threadIdx.x < IN_NODE * EMB_NF + EMB_NF) {
        int c = threadIdx.x - IN_NODE * EMB_NF;
        float acc = __ldg(&be[c]);
#pragma unroll
        for (int b = 0; b < OUT_NF; b++) {
            float hb = __ldg(&b2[b]);
#pragma unroll
            for (int a = 0; a < H_NF; a++)
                hb += __ldg(&b1[a]) * __ldg(&W2[a * OUT_NF + b]);
            acc += hb * __ldg(&We[b * EMB_NF + c]);
        }
        s_bf[c] = acc;
    }
    __syncthreads();

    int i = blockIdx.x * blockDim.x + threadIdx.x;
    if (i >= NN) return;
    float ex = s_bf[0], ey = s_bf[1];
#pragma unroll
    for (int r = 0; r < NREP; r++) {
        float2 v = g_acc[r][i];
        ex += v.x;  ey += v.y;
        g_acc[r][i] = make_float2(0.0f, 0.0f);   // restore invariant
    }
#pragma unroll
    for (int k = 0; k < IN_NODE; k++) {
        float nf = node_feats[i * IN_NODE + k];
        ex = fmaf(nf, s_wfn[k * 2 + 0], ex);
        ey = fmaf(nf, s_wfn[k * 2 + 1], ey);
    }
    g_emb2[i * 2 + 0] = ex;
    g_emb2[i * 2 + 1] = ey;
    out_emb[i * 2 + 0] = ex;
    out_emb[i * 2 + 1] = ey;
}

// ---------------------------------------------------------------------------
// Kernel 3: all-pairs adjacency, dot-product form (unchanged; runs at the
// LTS/DRAM write cap ~6.4 TB/s).
//   5d - 0.5 = K_i + a_j - 10*ei.ej ;  sigmoid(10d-1) = 0.5*tanh(5d-0.5)+0.5
// ---------------------------------------------------------------------------
__global__ void __launch_bounds__(256) k_pair(float* __restrict__ adj) {
    const int i0 = blockIdx.x * ROWS;
    float Kc[ROWS], bx[ROWS], by[ROWS];
#pragma unroll
    for (int r = 0; r < ROWS; r++) {
        float2 e = reinterpret_cast<const float2*>(g_emb2)[i0 + r];
        Kc[r] = fmaf(5.0f, fmaf(e.y, e.y, e.x * e.x), -0.5f);
        bx[r] = -10.0f * e.x;
        by[r] = -10.0f * e.y;
    }

    const float4* embq = reinterpret_cast<const float4*>(g_emb2);

    for (int g = threadIdx.x; g < NN / 4; g += blockDim.x) {
        const int j0 = g * 4;
        float2 ej[4];
        float  aj[4];
#pragma unroll
        for (int q = 0; q < 2; q++) {
            float4 v = embq[g * 2 + q];
            ej[q * 2 + 0] = make_float2(v.x, v.y);
            ej[q * 2 + 1] = make_float2(v.z, v.w);
        }
#pragma unroll
        for (int c = 0; c < 4; c++)
            aj[c] = 5.0f * fmaf(ej[c].y, ej[c].y, ej[c].x * ej[c].x);

#pragma unroll
        for (int r = 0; r < ROWS; r++) {
            float o[4];
#pragma unroll
            for (int c = 0; c < 4; c++) {
                float t = Kc[r] + aj[c];
                t = fmaf(bx[r], ej[c].x, t);
                t = fmaf(by[r], ej[c].y, t);
                float th;
                asm("tanh.approx.f32 %0, %1;" : "=f"(th) : "f"(t));
                o[c] = fmaf(th, 0.5f, 0.5f);
            }
            __stcs(reinterpret_cast<float4*>(adj + (size_t)(i0 + r) * NN + j0),
                   make_float4(o[0], o[1], o[2], o[3]));
        }
    }

    __syncthreads();
    if (threadIdx.x < ROWS) {
        int i = i0 + threadIdx.x;
        adj[(size_t)i * NN + i] = 0.0f;
    }
}

// ---------------------------------------------------------------------------
extern "C" void kernel_launch(void* const* d_in, const int* in_sizes, int n_in,
                              void* d_out, int out_size) {
    const float* node_feats = (const float*)d_in[0];
    const int*   edge_index = (const int*)d_in[1];
    const float* edge_attr  = (const float*)d_in[2];
    const float* W1 = (const float*)d_in[3];
    const float* b1 = (const float*)d_in[4];
    const float* W2 = (const float*)d_in[5];
    const float* b2 = (const float*)d_in[6];
    const float* We = (const float*)d_in[7];
    const float* be = (const float*)d_in[8];

    float* adj     = (float*)d_out;                       // [N, N]
    float* out_emb = (float*)d_out + (size_t)NN * NN;     // [N, 2]

    k_scatter<<<EE / EPT / 256, 256>>>(edge_index, edge_attr, W1, W2, We);
    k_emb<<<NN / 256, 256>>>(node_feats, W1, b1, W2, b2, We, be, out_emb);
    k_pair<<<NN / ROWS, 256>>>(adj);
}

// round 12
// speedup vs baseline: 1.2679x; 1.0167x over previous
#include <cuda_runtime.h>
#include <stdint.h>

#define NN      8192
#define EE      262144
#define IN_NODE 11
#define IN_EDGE 4
#define H_NF    4
#define OUT_NF  4
#define EMB_NF  2
#define NREP    8

#define ROWS    8          // rows per CTA in k_pair

// Scratch -------------------------------------------------------------------
// Invariant: g_acc is all-zero at entry of every kernel_launch call.
// (Zero at module load; k_emb re-zeroes after consuming.)
__device__ float2 g_acc[NREP][NN];
__device__ float  g_emb2[NN * EMB_NF];

// One fused-weight entry: wf[r][c] = sum_a W1[r][a] * (sum_b W2[a][b]*We[b][c])
__device__ __forceinline__ float fused_w_entry(const float* __restrict__ W1,
                                               const float* __restrict__ W2,
                                               const float* __restrict__ We,
                                               int r, int c) {
    float acc = 0.0f;
#pragma unroll
    for (int a = 0; a < H_NF; a++) {
        float m = 0.0f;
#pragma unroll
        for (int b = 0; b < OUT_NF; b++)
            m += __ldg(&W2[a * OUT_NF + b]) * __ldg(&We[b * EMB_NF + c]);
        acc += __ldg(&W1[r * H_NF + a]) * m;
    }
    return acc;
}

// ---------------------------------------------------------------------------
// Kernel 1: scatter. ONE edge per thread, 1024 CTAs (~86% occupancy) — the
// bandwidth-delay pool, not instruction count, limits this kernel. Warp 0
// computes the 8 fused edge-weights into smem once per CTA.
// ---------------------------------------------------------------------------
__global__ void __launch_bounds__(256) k_scatter(
        const int* __restrict__ edge_index, const float* __restrict__ edge_attr,
        const float* __restrict__ W1, const float* __restrict__ W2,
        const float* __restrict__ We) {
    __shared__ float s_wfe[IN_EDGE * EMB_NF];          // [r][c] -> r*2+c
    if (threadIdx.x < IN_EDGE * EMB_NF) {
        int r = threadIdx.x >> 1, c = threadIdx.x & 1;
        s_wfe[threadIdx.x] = fused_w_entry(W1, W2, We, IN_NODE + r, c);
    }
    __syncthreads();

    const int tid = blockIdx.x * blockDim.x + threadIdx.x;
    const int rep = blockIdx.x & (NREP - 1);

    int    rr = edge_index[tid];                         // edge_index[0][tid]
    float4 a  = reinterpret_cast<const float4*>(edge_attr)[tid];

    float cx = fmaf(a.x, s_wfe[0], fmaf(a.y, s_wfe[2], fmaf(a.z, s_wfe[4], a.w * s_wfe[6])));
    float cy = fmaf(a.x, s_wfe[1], fmaf(a.y, s_wfe[3], fmaf(a.z, s_wfe[5], a.w * s_wfe[7])));

    float2* dst = &g_acc[rep][rr];
    asm volatile("red.global.add.v2.f32 [%0], {%1, %2};"
                 :: "l"(dst), "f"(cx), "f"(cy) : "memory");
}

// ---------------------------------------------------------------------------
// Kernel 2: per-node embedding. Cooperative weight fusion in smem, lean
// per-node body; sums replicas and re-zeroes them.
// ---------------------------------------------------------------------------
__global__ void __launch_bounds__(256) k_emb(
        const float* __restrict__ node_feats,
        const float* __restrict__ W1, const float* __restrict__ b1,
        const float* __restrict__ W2, const float* __restrict__ b2,
        const float* __restrict__ We, const float* __restrict__ be,
        float* __restrict__ out_emb) {
    __shared__ float s_wfn[IN_NODE * EMB_NF];          // [k][c] -> k*2+c
    __shared__ float s_bf[EMB_NF];
    if (threadIdx.x < IN_NODE * EMB_NF) {
        int k = threadIdx.x >> 1, c = threadIdx.x & 1;
        s_wfn[threadIdx.x] = fused_w_entry(W1, W2, We, k, c);
    } else if (threadIdx.x < IN_NODE * EMB_NF + EMB_NF) {
        int c = threadIdx.x - IN_NODE * EMB_NF;
        float acc = __ldg(&be[c]);
#pragma unroll
        for (int b = 0; b < OUT_NF; b++) {
            float hb = __ldg(&b2[b]);
#pragma unroll
            for (int a = 0; a < H_NF; a++)
                hb += __ldg(&b1[a]) * __ldg(&W2[a * OUT_NF + b]);
            acc += hb * __ldg(&We[b * EMB_NF + c]);
        }
        s_bf[c] = acc;
    }
    __syncthreads();

    int i = blockIdx.x * blockDim.x + threadIdx.x;
    if (i >= NN) return;
    float ex = s_bf[0], ey = s_bf[1];
#pragma unroll
    for (int r = 0; r < NREP; r++) {
        float2 v = g_acc[r][i];
        ex += v.x;  ey += v.y;
        g_acc[r][i] = make_float2(0.0f, 0.0f);   // restore invariant
    }
#pragma unroll
    for (int k = 0; k < IN_NODE; k++) {
        float nf = node_feats[i * IN_NODE + k];
        ex = fmaf(nf, s_wfn[k * 2 + 0], ex);
        ey = fmaf(nf, s_wfn[k * 2 + 1], ey);
    }
    g_emb2[i * 2 + 0] = ex;
    g_emb2[i * 2 + 1] = ey;
    out_emb[i * 2 + 0] = ex;
    out_emb[i * 2 + 1] = ey;
}

// ---------------------------------------------------------------------------
// Kernel 3: all-pairs adjacency, dot-product form (unchanged; runs near the
// DRAM write cap).
//   5d - 0.5 = K_i + a_j - 10*ei.ej ;  sigmoid(10d-1) = 0.5*tanh(5d-0.5)+0.5
// ---------------------------------------------------------------------------
__global__ void __launch_bounds__(256) k_pair(float* __restrict__ adj) {
    const int i0 = blockIdx.x * ROWS;
    float Kc[ROWS], bx[ROWS], by[ROWS];
#pragma unroll
    for (int r = 0; r < ROWS; r++) {
        float2 e = reinterpret_cast<const float2*>(g_emb2)[i0 + r];
        Kc[r] = fmaf(5.0f, fmaf(e.y, e.y, e.x * e.x), -0.5f);
        bx[r] = -10.0f * e.x;
        by[r] = -10.0f * e.y;
    }

    const float4* embq = reinterpret_cast<const float4*>(g_emb2);

    for (int g = threadIdx.x; g < NN / 4; g += blockDim.x) {
        const int j0 = g * 4;
        float2 ej[4];
        float  aj[4];
#pragma unroll
        for (int q = 0; q < 2; q++) {
            float4 v = embq[g * 2 + q];
            ej[q * 2 + 0] = make_float2(v.x, v.y);
            ej[q * 2 + 1] = make_float2(v.z, v.w);
        }
#pragma unroll
        for (int c = 0; c < 4; c++)
            aj[c] = 5.0f * fmaf(ej[c].y, ej[c].y, ej[c].x * ej[c].x);

#pragma unroll
        for (int r = 0; r < ROWS; r++) {
            float o[4];
#pragma unroll
            for (int c = 0; c < 4; c++) {
                float t = Kc[r] + aj[c];
                t = fmaf(bx[r], ej[c].x, t);
                t = fmaf(by[r], ej[c].y, t);
                float th;
                asm("tanh.approx.f32 %0, %1;" : "=f"(th) : "f"(t));
                o[c] = fmaf(th, 0.5f, 0.5f);
            }
            __stcs(reinterpret_cast<float4*>(adj + (size_t)(i0 + r) * NN + j0),
                   make_float4(o[0], o[1], o[2], o[3]));
        }
    }

    __syncthreads();
    if (threadIdx.x < ROWS) {
        int i = i0 + threadIdx.x;
        adj[(size_t)i * NN + i] = 0.0f;
    }
}

// ---------------------------------------------------------------------------
extern "C" void kernel_launch(void* const* d_in, const int* in_sizes, int n_in,
                              void* d_out, int out_size) {
    const float* node_feats = (const float*)d_in[0];
    const int*   edge_index = (const int*)d_in[1];
    const float* edge_attr  = (const float*)d_in[2];
    const float* W1 = (const float*)d_in[3];
    const float* b1 = (const float*)d_in[4];
    const float* W2 = (const float*)d_in[5];
    const float* b2 = (const float*)d_in[6];
    const float* We = (const float*)d_in[7];
    const float* be = (const float*)d_in[8];

    float* adj     = (float*)d_out;                       // [N, N]
    float* out_emb = (float*)d_out + (size_t)NN * NN;     // [N, 2]

    k_scatter<<<EE / 256, 256>>>(edge_index, edge_attr, W1, W2, We);
    k_emb<<<NN / 256, 256>>>(node_feats, W1, b1, W2, b2, We, be, out_emb);
    k_pair<<<NN / ROWS, 256>>>(adj);
}